// round 1
// baseline (speedup 1.0000x reference)
#include <cuda_runtime.h>

#define N_GAUSS   16
#define N_ATOMS   3072
#define N_GRAPHS  64
#define K_GRID    4096
#define TILE      64
#define BLOCK     256

// Per-graph atom range boundaries: g_start[g] .. g_start[g+1]
__device__ int g_start[N_GRAPHS + 1];

__device__ __forceinline__ float ex2f(float x) {
    float y;
    asm("ex2.approx.ftz.f32 %0, %1;" : "=f"(y) : "f"(x));
    return y;
}

// Prep: detect batch dtype (int64 vs int32) and compute per-graph ranges.
// If batch is int64 (little-endian, values in [0,64)), every odd 32-bit word
// within the first N_ATOMS words is the zero high-half. If batch is int32
// (sorted, reaching ~63), odd words cannot all be zero.
__global__ void prep_kernel(const int* __restrict__ braw) {
    __shared__ int any_odd_nonzero;
    if (threadIdx.x == 0) any_odd_nonzero = 0;
    __syncthreads();

    int local = 0;
    for (int i = 1 + 2 * (int)threadIdx.x; i < N_ATOMS; i += 2 * (int)blockDim.x)
        local |= braw[i];
    if (local) atomicOr(&any_odd_nonzero, 1);
    __syncthreads();

    const bool is32 = (any_odd_nonzero != 0);

    if (threadIdx.x <= N_GRAPHS) {
        int g = threadIdx.x;
        int lo = 0, hi = N_ATOMS;
        while (lo < hi) {
            int m = (lo + hi) >> 1;
            int v = is32 ? braw[m] : braw[2 * m];  // low word of int64 suffices
            if (v < g) lo = m + 1; else hi = m;
        }
        g_start[g] = lo;
    }
}

__global__ __launch_bounds__(BLOCK)
void gauss_kernel(const float* __restrict__ coeff,
                  const float* __restrict__ atom_coord,
                  const float* __restrict__ grid,
                  float* __restrict__ out) {
    __shared__ float sx[TILE], sy[TILE], sz[TILE];
    __shared__ float sw[N_GAUSS][TILE + 1];

    const int g = blockIdx.y;
    const int k = blockIdx.x * BLOCK + threadIdx.x;

    const int start = g_start[g];
    const int end   = g_start[g + 1];

    // Grid point for this thread
    const long long gidx = (long long)(g * K_GRID + k) * 3;
    const float px = grid[gidx + 0];
    const float py = grid[gidx + 1];
    const float pz = grid[gidx + 2];

    float acc0 = 0.f, acc1 = 0.f, acc2 = 0.f, acc3 = 0.f;

    for (int base = start; base < end; base += TILE) {
        const int cnt = min(TILE, end - base);

        __syncthreads();  // protect shared from previous iteration's readers

        // Stage atom coords
        for (int a = threadIdx.x; a < cnt; a += BLOCK) {
            const float* ac = atom_coord + (long long)(base + a) * 3;
            sx[a] = ac[0];
            sy[a] = ac[1];
            sz[a] = ac[2];
        }
        // Stage coeff pre-multiplied by sigma_r (compile-time folded per j)
        for (int idx = threadIdx.x; idx < cnt * N_GAUSS; idx += BLOCK) {
            const int a = idx >> 4;
            const int j = idx & 15;
            const float sigma = 0.5f + 0.3f * (float)j;
            const float t = sigma * 2.5066282746310002f;  // sigma*sqrt(2*pi)
            const float sr = 1.0f / (t * t * t);
            sw[j][a] = coeff[(long long)(base + a) * N_GAUSS + j] * sr;
        }
        __syncthreads();

        for (int a = 0; a < cnt; a++) {
            const float dx = px - sx[a];
            const float dy = py - sy[a];
            const float dz = pz - sz[a];
            const float nr2 = -fmaf(dx, dx, fmaf(dy, dy, dz * dz));

            #pragma unroll
            for (int j = 0; j < N_GAUSS; j += 4) {
                // c2[j] = log2(e) / sigma_j^2 — compile-time immediate after unroll
                const float s0 = 0.5f + 0.3f * (float)(j + 0);
                const float s1 = 0.5f + 0.3f * (float)(j + 1);
                const float s2 = 0.5f + 0.3f * (float)(j + 2);
                const float s3 = 0.5f + 0.3f * (float)(j + 3);
                const float c0 = 1.4426950408889634f / (s0 * s0);
                const float c1 = 1.4426950408889634f / (s1 * s1);
                const float c2 = 1.4426950408889634f / (s2 * s2);
                const float c3 = 1.4426950408889634f / (s3 * s3);
                acc0 = fmaf(sw[j + 0][a], ex2f(nr2 * c0), acc0);
                acc1 = fmaf(sw[j + 1][a], ex2f(nr2 * c1), acc1);
                acc2 = fmaf(sw[j + 2][a], ex2f(nr2 * c2), acc2);
                acc3 = fmaf(sw[j + 3][a], ex2f(nr2 * c3), acc3);
            }
        }
    }

    out[(long long)g * K_GRID + k] = (acc0 + acc1) + (acc2 + acc3);
}

extern "C" void kernel_launch(void* const* d_in, const int* in_sizes, int n_in,
                              void* d_out, int out_size) {
    const float* coeff      = (const float*)d_in[0];
    const float* atom_coord = (const float*)d_in[1];
    const float* grid       = (const float*)d_in[2];
    const int*   batch_raw  = (const int*)d_in[3];  // int64 or int32, detected on device
    float* out = (float*)d_out;

    prep_kernel<<<1, 128>>>(batch_raw);

    dim3 gridDim(K_GRID / BLOCK, N_GRAPHS);
    gauss_kernel<<<gridDim, BLOCK>>>(coeff, atom_coord, grid, out);
}